// round 14
// baseline (speedup 1.0000x reference)
#include <cuda_runtime.h>

// ---------------------------------------------------------------------------
// Griffin-Lim, fully fused on-GPU.
//   mel (8,80,1024), angles (8,513,1024), inv_fb (513,80) -> out (8,261888)
// 60 iterations of istft -> stft -> phase projection in the FRAMES domain.
// Iteration kernel: radix-8^3 512-pt FFT with f32x2 PACKED math -- each
// 64-thread lane processes TWO frames (packed in 64-bit regs). All complex
// multiplies FMA-contracted; twiddle chains depth<=3 from sincospif anchors.
// 4 blocks/SM (forced 64-reg target; spills absorbed by L1).
// ---------------------------------------------------------------------------

#define BB     8
#define TT     1024          // frames
#define NFFTC  1024
#define NFC    513
#define HOPC   256
#define LPADL  262912        // NFFT + (TT-1)*HOP
#define LCROP  261888        // (T-1)*HOP
#define FPB    8             // frames per block (4 lanes x 2 packed)
#define TILE   2816          // HOP*(FPB-1)+NFFT
#define REDGE  262400        // 512 + LCROP
#define MIRR   524798        // 2*LCROP + 1022
#define NITER  60

#define P8(x)  ((x) + ((x) >> 3))   // smem padding for exchange buffers
#define PBUF   576                  // P8(511)=574 < 576

// per-lane barrier: 64 threads (2 warps) of lane `sub`
#define LBAR(sub) asm volatile("bar.sync %0, 64;" :: "r"((sub) + 1) : "memory")

typedef unsigned long long ull;

// ---- f32x2 packed primitives (sm_100+) ----
__device__ __forceinline__ ull PK2(float a, float b) {
    ull o; asm("mov.b64 %0,{%1,%2};" : "=l"(o) : "f"(a), "f"(b)); return o;
}
__device__ __forceinline__ void UPK2(ull v, float& a, float& b) {
    asm("mov.b64 {%0,%1},%2;" : "=f"(a), "=f"(b) : "l"(v));
}
#define FADD2(o,a,b)   asm("add.rn.f32x2 %0,%1,%2;"    : "=l"(o) : "l"(a), "l"(b))
#define FSUB2(o,a,b)   asm("sub.rn.f32x2 %0,%1,%2;"    : "=l"(o) : "l"(a), "l"(b))
#define FMUL2(o,a,b)   asm("mul.rn.f32x2 %0,%1,%2;"    : "=l"(o) : "l"(a), "l"(b))
#define FFMA2(o,a,b,c) asm("fma.rn.f32x2 %0,%1,%2,%3;" : "=l"(o) : "l"(a), "l"(b), "l"(c))

// Scratch (device globals are the sanctioned scratch mechanism)
__device__ float  g_F[2][BB * TT * NFFTC];   // istft frames, ping-pong (67 MB)
__device__ float  g_mag[BB * TT * NFC];      // target magnitudes [b][t][f]
__device__ float  g_win[NFFTC];
__device__ float2 g_tw[NFFTC];               // e^{-2*pi*i*m/1024} (init kernels only)
__device__ float  g_invenv[LPADL];           // 1 / window-envelope (or 1.0)

__device__ __forceinline__ void cmul(float ar, float ai, float br, float bi,
                                     float& cr, float& ci) {
    cr = ar * br - ai * bi;
    ci = ar * bi + ai * br;
}

// ===========================================================================
// Packed radix-8 register FFT (512 = 8*8*8, 64 threads, 2 frames per thread)
// ===========================================================================

template <bool INV>
__device__ __forceinline__ void fft8p(ull* vr, ull* vi) {
    const ull CC = PK2(0.70710678118654752440f, 0.70710678118654752440f);
    ull a0r,a0i,a1r,a1i,b0r,b0i,b1r,b1i;
    FADD2(a0r,vr[0],vr[4]); FADD2(a0i,vi[0],vi[4]);
    FSUB2(a1r,vr[0],vr[4]); FSUB2(a1i,vi[0],vi[4]);
    FADD2(b0r,vr[2],vr[6]); FADD2(b0i,vi[2],vi[6]);
    FSUB2(b1r,vr[2],vr[6]); FSUB2(b1i,vi[2],vi[6]);
    ull E0r,E0i,E1r,E1i,E2r,E2i,E3r,E3i;
    FADD2(E0r,a0r,b0r); FADD2(E0i,a0i,b0i);
    FSUB2(E2r,a0r,b0r); FSUB2(E2i,a0i,b0i);
    if (!INV) {
        FADD2(E1r,a1r,b1i); FSUB2(E1i,a1i,b1r);
        FSUB2(E3r,a1r,b1i); FADD2(E3i,a1i,b1r);
    } else {
        FSUB2(E1r,a1r,b1i); FADD2(E1i,a1i,b1r);
        FADD2(E3r,a1r,b1i); FSUB2(E3i,a1i,b1r);
    }
    ull c0r,c0i,c1r,c1i,d0r,d0i,d1r,d1i;
    FADD2(c0r,vr[1],vr[5]); FADD2(c0i,vi[1],vi[5]);
    FSUB2(c1r,vr[1],vr[5]); FSUB2(c1i,vi[1],vi[5]);
    FADD2(d0r,vr[3],vr[7]); FADD2(d0i,vi[3],vi[7]);
    FSUB2(d1r,vr[3],vr[7]); FSUB2(d1i,vi[3],vi[7]);
    ull O0r,O0i,O1r,O1i,O2r,O2i,O3r,O3i;
    FADD2(O0r,c0r,d0r); FADD2(O0i,c0i,d0i);
    FSUB2(O2r,c0r,d0r); FSUB2(O2i,c0i,d0i);
    if (!INV) {
        FADD2(O1r,c1r,d1i); FSUB2(O1i,c1i,d1r);
        FSUB2(O3r,c1r,d1i); FADD2(O3i,c1i,d1r);
    } else {
        FSUB2(O1r,c1r,d1i); FADD2(O1i,c1i,d1r);
        FADD2(O3r,c1r,d1i); FSUB2(O3i,c1i,d1r);
    }
    FADD2(vr[0],E0r,O0r); FADD2(vi[0],E0i,O0i);
    FSUB2(vr[4],E0r,O0r); FSUB2(vi[4],E0i,O0i);
    ull u,t1r,t1i;
    if (!INV) { FADD2(u,O1r,O1i); FMUL2(t1r,u,CC); FSUB2(u,O1i,O1r); FMUL2(t1i,u,CC); }
    else      { FSUB2(u,O1r,O1i); FMUL2(t1r,u,CC); FADD2(u,O1i,O1r); FMUL2(t1i,u,CC); }
    FADD2(vr[1],E1r,t1r); FADD2(vi[1],E1i,t1i);
    FSUB2(vr[5],E1r,t1r); FSUB2(vi[5],E1i,t1i);
    if (!INV) {
        FADD2(vr[2],E2r,O2i); FSUB2(vi[2],E2i,O2r);
        FSUB2(vr[6],E2r,O2i); FADD2(vi[6],E2i,O2r);
    } else {
        FSUB2(vr[2],E2r,O2i); FADD2(vi[2],E2i,O2r);
        FADD2(vr[6],E2r,O2i); FSUB2(vi[6],E2i,O2r);
    }
    ull m3a, m3b;
    if (!INV) {
        FSUB2(u,O3i,O3r); FMUL2(m3a,u,CC);    // m3a = C(O3i-O3r)
        FADD2(u,O3r,O3i); FMUL2(m3b,u,CC);    // m3b = C(O3r+O3i)
        FADD2(vr[3],E3r,m3a); FSUB2(vi[3],E3i,m3b);
        FSUB2(vr[7],E3r,m3a); FADD2(vi[7],E3i,m3b);
    } else {
        FADD2(u,O3r,O3i); FMUL2(m3b,u,CC);    // m3b = C(O3r+O3i)
        FSUB2(u,O3r,O3i); FMUL2(m3a,u,CC);    // m3a = C(O3r-O3i)
        FSUB2(vr[3],E3r,m3b); FADD2(vi[3],E3i,m3a);
        FADD2(vr[7],E3r,m3b); FSUB2(vi[7],E3i,m3a);
    }
}

__device__ __forceinline__ void load8p(const ull* eR, const ull* eI, int j,
                                       ull* vr, ull* vi) {
#pragma unroll
    for (int q = 0; q < 8; q++) {
        int d = j + 64 * q;
        vr[q] = eR[P8(d)];
        vi[q] = eI[P8(d)];
    }
}

template <int NS>
__device__ __forceinline__ void store8p(ull* eR, ull* eI, int j,
                                        const ull* vr, const ull* vi) {
    int base = ((j & ~(NS - 1)) << 3) + (j & (NS - 1));
#pragma unroll
    for (int q = 0; q < 8; q++) {
        int d = base + q * NS;
        eR[P8(d)] = vr[q];
        eI[P8(d)] = vi[q];
    }
}

// Packed Stockham stage twiddle: v[q] *= w^q, w = e^{-i pi ang_pi} (fwd) or
// its conjugate (inv). Powers computed in scalar (compiler-contracted FMA)
// from two sincospif anchors (w^1 and w^4): chain depth <= 3.
// Application is FMA-contracted packed cmul (single rounding per component).
template <bool INV>
__device__ __forceinline__ void twiddle8p(ull* vr, ull* vi, float ang_pi) {
    float c1, s1, c4, s4;
    sincospif(ang_pi, &s1, &c1);
    sincospif(4.0f * ang_pi, &s4, &c4);
    if (!INV) { s1 = -s1; s4 = -s4; }
    float cr[8], ci[8];
    cr[1] = c1; ci[1] = s1;
    cr[2] = c1 * c1 - s1 * s1;           ci[2] = 2.0f * c1 * s1;
    cr[3] = cr[2] * c1 - ci[2] * s1;     ci[3] = cr[2] * s1 + ci[2] * c1;
    cr[4] = c4; ci[4] = s4;
    cr[5] = c4 * c1 - s4 * s1;           ci[5] = c4 * s1 + s4 * c1;
    cr[6] = c4 * cr[2] - s4 * ci[2];     ci[6] = c4 * ci[2] + s4 * cr[2];
    cr[7] = c4 * cr[3] - s4 * ci[3];     ci[7] = c4 * ci[3] + s4 * cr[3];
#pragma unroll
    for (int q = 1; q < 8; q++) {
        ull Wr  = PK2(cr[q], cr[q]);
        ull Wi  = PK2(ci[q], ci[q]);
        ull Win = PK2(-ci[q], -ci[q]);
        ull t, u, tr, ti;
        FMUL2(t, vi[q], Win); FFMA2(tr, vr[q], Wr, t);   // vr*Wr - vi*Wi
        FMUL2(u, vr[q], Wi);  FFMA2(ti, vi[q], Wr, u);   // vr*Wi + vi*Wr
        vr[q] = tr; vi[q] = ti;
    }
}

// ===========================================================================
// Radix-4 shared-memory FFT (kept only for the one-time init kernel)
// ===========================================================================
template <int NS, bool INV>
__device__ __forceinline__ void stage4(const float* sr, const float* si,
                                       float* dr, float* di,
                                       const float2* tw, int j) {
    int i = j & (NS - 1);
    float x0r = sr[j],       x0i = si[j];
    float x1r = sr[j + 128], x1i = si[j + 128];
    float x2r = sr[j + 256], x2i = si[j + 256];
    float x3r = sr[j + 384], x3i = si[j + 384];
    if (NS > 1) {
        int ti = i * (256 / NS);
        float2 w1 = tw[ti], w2 = tw[2 * ti], w3 = tw[3 * ti];
        float w1i = INV ? -w1.y : w1.y;
        float w2i = INV ? -w2.y : w2.y;
        float w3i = INV ? -w3.y : w3.y;
        float tr, ti2;
        cmul(x1r, x1i, w1.x, w1i, tr, ti2); x1r = tr; x1i = ti2;
        cmul(x2r, x2i, w2.x, w2i, tr, ti2); x2r = tr; x2i = ti2;
        cmul(x3r, x3i, w3.x, w3i, tr, ti2); x3r = tr; x3i = ti2;
    }
    float t0r = x0r + x2r, t0i = x0i + x2i;
    float t1r = x0r - x2r, t1i = x0i - x2i;
    float t2r = x1r + x3r, t2i = x1i + x3i;
    float t3r = x1r - x3r, t3i = x1i - x3i;
    float jr = INV ? -t3i : t3i;
    float ji = INV ?  t3r : -t3r;
    int idxD = ((j & ~(NS - 1)) << 2) + i;
    dr[idxD]          = t0r + t2r;  di[idxD]          = t0i + t2i;
    dr[idxD + NS]     = t1r + jr;   di[idxD + NS]     = t1i + ji;
    dr[idxD + 2 * NS] = t0r - t2r;  di[idxD + 2 * NS] = t0i - t2i;
    dr[idxD + 3 * NS] = t1r - jr;   di[idxD + 3 * NS] = t1i - ji;
}

template <bool INV>
__device__ void fft512(float* r0, float* i0, float* r1, float* i1,
                       const float2* tw, int j) {
    __syncthreads();
    stage4<1,  INV>(r0, i0, r1, i1, tw, j); __syncthreads();
    stage4<4,  INV>(r1, i1, r0, i0, tw, j); __syncthreads();
    stage4<16, INV>(r0, i0, r1, i1, tw, j); __syncthreads();
    stage4<64, INV>(r1, i1, r0, i0, tw, j); __syncthreads();
#pragma unroll
    for (int q = 0; q < 2; q++) {
        int jj = j + q * 128;
        float x0r = r0[jj],       x0i = i0[jj];
        float x1r = r0[jj + 256], x1i = i0[jj + 256];
        float2 w  = tw[2 * jj];
        float wi = INV ? -w.y : w.y;
        float yr, yi;
        cmul(x1r, x1i, w.x, wi, yr, yi);
        r1[jj]       = x0r + yr;  i1[jj]       = x0i + yi;
        r1[jj + 256] = x0r - yr;  i1[jj + 256] = x0i - yi;
    }
    __syncthreads();
}

__device__ __forceinline__ void write_zprime(int k, float Pr, float Pi,
                                             float Qr, float Qi, float2 w,
                                             float* r0, float* i0) {
    float Ser = 0.5f * (Pr + Qr), Sei = 0.5f * (Pi - Qi);
    float Sdr = 0.5f * (Pr - Qr), Sdi = 0.5f * (Pi + Qi);
    float Ur = Sdr * w.x + Sdi * w.y;
    float Ui = Sdi * w.x - Sdr * w.y;
    r0[k] = Ser - Ui;
    i0[k] = Sei + Ur;
    if (k >= 1 && k <= 255) {
        r0[512 - k] = Ser + Ui;
        i0[512 - k] = Ur - Sei;
    }
}

// ---------------------------------------------------------------------------
// Table init: window, twiddles, inverse OLA envelope
// ---------------------------------------------------------------------------
__global__ void gl_init_tables() {
    int idx = blockIdx.x * blockDim.x + threadIdx.x;
    if (idx < NFFTC) {
        g_win[idx] = 0.5f - 0.5f * cospif(idx * (1.0f / 512.0f));
        float s, c;
        sincospif(idx * (1.0f / 512.0f), &s, &c);
        g_tw[idx] = make_float2(c, -s);
    }
    if (idx < LPADL) {
        int m   = idx;
        int thi = min(m >> 8, TT - 1);
        int tlo = (m >= 768) ? ((m - 768) >> 8) : 0;
        float e = 0.0f;
        for (int tf = tlo; tf <= thi; ++tf) {
            int kk  = m - (tf << 8);
            float w = 0.5f - 0.5f * cospif(kk * (1.0f / 512.0f));
            e += w * w;
        }
        g_invenv[idx] = (e > 1e-11f) ? (1.0f / e) : 1.0f;
    }
}

// ---------------------------------------------------------------------------
// mag = clip(inv_fb @ exp(mel), 0) -> g_mag[b][t][f]   (one-time)
// ---------------------------------------------------------------------------
__global__ __launch_bounds__(256) void gl_mag(const float* __restrict__ mel,
                                              const float* __restrict__ fb) {
    __shared__ float em[80 * 128];
    int tid = threadIdx.x;
    int bx  = blockIdx.x;
    int b   = bx >> 3;
    int t0  = (bx & 7) * 128;
    for (int idx = tid; idx < 80 * 128; idx += 256) {
        int m = idx >> 7, t = idx & 127;
        em[idx] = expf(mel[(b * 80 + m) * TT + t0 + t]);
    }
    __syncthreads();
    int t = tid & 127, half = tid >> 7;
    for (int f = half; f < NFC; f += 2) {
        const float* fbp = fb + f * 80;
        float acc = 0.0f;
#pragma unroll 16
        for (int m = 0; m < 80; m++) acc += fbp[m] * em[(m << 7) + t];
        g_mag[(b * TT + t0 + t) * NFC + f] = fmaxf(acc, 0.0f);
    }
}

// ---------------------------------------------------------------------------
// F0 = irfft(mag * e^{2 pi i angles}) * win   (one-time, radix-4 path)
// ---------------------------------------------------------------------------
__global__ __launch_bounds__(128) void gl_init_frames(const float* __restrict__ angles) {
    __shared__ float  r0[512], i0[512], r1[512], i1[512];
    __shared__ float  swin[NFFTC];
    __shared__ float2 stw[NFFTC];
    int tid = threadIdx.x;
    int bx  = blockIdx.x;
    int b   = bx >> 10;
    int t   = bx & 1023;
    for (int idx = tid; idx < NFFTC; idx += 128) {
        swin[idx] = g_win[idx];
        stw[idx]  = g_tw[idx];
    }
    const float* mp = &g_mag[(b * TT + t) * NFC];
    __syncthreads();
    for (int k = tid; k < 257; k += 128) {
        float a1 = angles[(b * NFC + k) * TT + t];
        float a2 = angles[(b * NFC + 512 - k) * TT + t];
        float s, c;
        sincospif(2.0f * a1, &s, &c);
        float m1 = mp[k];
        float Pr = m1 * c, Pi = m1 * s;
        sincospif(2.0f * a2, &s, &c);
        float m2 = mp[512 - k];
        float Qr = m2 * c, Qi = m2 * s;
        if (k == 0) { Pi = 0.0f; Qi = 0.0f; }
        write_zprime(k, Pr, Pi, Qr, Qi, stw[k], r0, i0);
    }
    fft512<true>(r0, i0, r1, i1, stw, tid);
    float* Fo = &g_F[0][(b * TT + t) * NFFTC];
    const float sc = 1.0f / 512.0f;
    for (int idx = tid; idx < NFFTC; idx += 128) {
        float v = (idx & 1) ? i1[idx >> 1] : r1[idx >> 1];
        Fo[idx] = v * swin[idx] * sc;
    }
}

// ---------------------------------------------------------------------------
// One Griffin-Lim step. 4 lanes x 64 threads, 2 frames per thread (f32x2).
// Single in-place exchange buffer, per-lane barriers, 4 blocks/SM.
// ---------------------------------------------------------------------------
__global__ __launch_bounds__(256, 4) void gl_iter8(int src, int dst) {
    __shared__ float  sy[TILE];
    __shared__ ull    exR[4][PBUF];
    __shared__ ull    exI[4][PBUF];
    __shared__ float2 swin2[512];
    int tid = threadIdx.x;
    int sub = tid >> 6;                 // lane 0..3 (2 frames each)
    int j   = tid & 63;                 // thread within lane
    int bx  = blockIdx.x;
    int b   = bx >> 7;                  // 128 groups per batch
    int g   = bx & 127;
    int t0  = g * FPB;
    int n0  = t0 * HOPC;

    const float2* gw2 = (const float2*)g_win;
    for (int idx = tid; idx < 512; idx += 256) swin2[idx] = gw2[idx];

    // --- gather normalized, reflect-padded signal tile (block-wide) ---
    const float* Fs = g_F[src] + b * (TT * NFFTC);
    if (g != 0 && g != 127) {
        for (int u = tid; u < TILE; u += 256) {
            int m = n0 + u;
            const float* p = Fs + m + (((m >> 8) - 3) * 768);
            float acc = p[0] + p[768] + p[1536] + p[2304];
            sy[u] = acc * g_invenv[m];
        }
    } else {
        for (int u = tid; u < TILE; u += 256) {
            int m = n0 + u;
            if (m < 512)         m = 1024 - m;      // left reflect
            else if (m >= REDGE) m = MIRR - m;      // right reflect
            int thi = min(m >> 8, TT - 1);
            int tlo = (m >= 768) ? ((m - 768) >> 8) : 0;
            float acc = 0.0f;
#pragma unroll
            for (int qq = 0; qq < 4; qq++) {
                int tf = tlo + qq;
                if (tf <= thi) acc += Fs[tf * NFFTC + (m - (tf << 8))];
            }
            sy[u] = acc * g_invenv[m];
        }
    }
    __syncthreads();

    ull* eR = exR[sub];
    ull* eI = exI[sub];
    int tA   = t0 + 2 * sub;            // frame A (packed low)
    int offA = 2 * sub * HOPC;
    int offB = offA + HOPC;

    ull vr[8], vi[8];

    // ---- forward FFT (packed real-1024 as complex-512, 2 frames) ----
    // stage 1 (Ns=1): pack straight from tile
#pragma unroll
    for (int q = 0; q < 8; q++) {
        int m = j + 64 * q;
        float2 w = swin2[m];
        ull wx = PK2(w.x, w.x), wy = PK2(w.y, w.y);
        ull rr = PK2(sy[offA + 2 * m],     sy[offB + 2 * m]);
        ull ii = PK2(sy[offA + 2 * m + 1], sy[offB + 2 * m + 1]);
        FMUL2(vr[q], rr, wx);
        FMUL2(vi[q], ii, wy);
    }
    fft8p<false>(vr, vi);
    store8p<1>(eR, eI, j, vr, vi);
    LBAR(sub);

    // stage 2 (Ns=8): in-place (load-all -> barrier -> store)
    load8p(eR, eI, j, vr, vi);
    LBAR(sub);
    twiddle8p<false>(vr, vi, (j & 7) * (1.0f / 32.0f));
    fft8p<false>(vr, vi);
    store8p<8>(eR, eI, j, vr, vi);
    LBAR(sub);

    // stage 3 (Ns=64): reads and writes the SAME per-thread slots
    load8p(eR, eI, j, vr, vi);
    twiddle8p<false>(vr, vi, j * (1.0f / 256.0f));
    fft8p<false>(vr, vi);
#pragma unroll
    for (int q = 0; q < 8; q++) {
        int d = j + 64 * q;
        eR[P8(d)] = vr[q];
        eI[P8(d)] = vi[q];
    }
    LBAR(sub);

    // ---- phase projection fused with inverse stage-1 input ----
    // (cos,sin)(pi k/512) for k=j+64q: two sincospif anchors (q=0, q=4),
    // chained by +pi/8 rotation (scalar, compiler-contracted), depth <= 3.
    const float* mpA = g_mag + (b * TT + tA) * NFC;
    const float* mpB = mpA + NFC;
    const float C8 = 0.92387953251128675613f;   // cos(pi/8)
    const float S8 = 0.38268343236508977173f;   // sin(pi/8)
    const ull H2   = PK2(0.5f, 0.5f);
    const ull EPS2 = PK2(1e-16f, 1e-16f);
    float a0s, a0c, a4s, a4c;
    sincospif(j * (1.0f / 512.0f), &a0s, &a0c);
    sincospif((j + 256) * (1.0f / 512.0f), &a4s, &a4c);
    float cs = a0c, ss = a0s;
#pragma unroll
    for (int q = 0; q < 8; q++) {
        if (q == 4) { cs = a4c; ss = a4s; }     // re-anchor
        int k  = j + 64 * q;
        int kc = (512 - k) & 511;
        ull Pr = eR[P8(k)],  Pi = eI[P8(k)];
        ull Qr = eR[P8(kc)], Qi = eI[P8(kc)];
        ull u, Ser, Sei, Sdr, Sdi;
        FADD2(u, Pr, Qr); FMUL2(Ser, u, H2);
        FSUB2(u, Pi, Qi); FMUL2(Sei, u, H2);
        FSUB2(u, Pr, Qr); FMUL2(Sdr, u, H2);
        FADD2(u, Pi, Qi); FMUL2(Sdi, u, H2);
        ull c2 = PK2(cs, cs), s2 = PK2(ss, ss), s2n = PK2(-ss, -ss);
        ull A, Bp;
        FMUL2(u, Sdr, s2n); FFMA2(A, Sdi, c2, u);      // A  = Sdi*c - Sdr*s
        FMUL2(u, Sdi, s2);  FFMA2(Bp, Sdr, c2, u);     // Bp = Sdr*c + Sdi*s = -Bv
        ull Xr, Xi, Yr, Yip;
        FADD2(Xr, Ser, A);  FSUB2(Xi, Sei, Bp);        // X[k]
        FSUB2(Yr, Ser, A);  FADD2(Yip, Bp, Sei);       // Yip = -X[512-k].imag
        ull d;
        FMUL2(d, Xr, Xr); FFMA2(d, Xi, Xi, d); FADD2(d, d, EPS2);
        float dA, dB; UPK2(d, dA, dB);
        ull rs = PK2(rsqrtf(dA), rsqrtf(dB));
        ull gk; FMUL2(gk, PK2(mpA[k], mpB[k]), rs);
        FMUL2(d, Yr, Yr); FFMA2(d, Yip, Yip, d); FADD2(d, d, EPS2);
        UPK2(d, dA, dB);
        rs = PK2(rsqrtf(dA), rsqrtf(dB));
        ull gq; FMUL2(gq, PK2(mpA[512 - k], mpB[512 - k]), rs);
        ull Gpr, Gpi, Gqr, Gqip;
        FMUL2(Gpr, gk, Xr); FMUL2(Gpi, gk, Xi);
        FMUL2(Gqr, gq, Yr); FMUL2(Gqip, gq, Yip);      // Gqip = -Gqi
        ull Ser2, Sei2, Sdr2, Sdi2;
        FADD2(u, Gpr, Gqr);  FMUL2(Ser2, u, H2);
        FADD2(u, Gpi, Gqip); FMUL2(Sei2, u, H2);       // 0.5(Gpi - Gqi)
        FSUB2(u, Gpr, Gqr);  FMUL2(Sdr2, u, H2);
        FSUB2(u, Gpi, Gqip); FMUL2(Sdi2, u, H2);       // 0.5(Gpi + Gqi)
        ull Ur, Ui;
        FMUL2(u, Sdi2, s2n); FFMA2(Ur, Sdr2, c2, u);   // Ur = Sdr2*c - Sdi2*s
        FMUL2(u, Sdr2, s2);  FFMA2(Ui, Sdi2, c2, u);   // Ui = Sdi2*c + Sdr2*s
        FSUB2(vr[q], Ser2, Ui);                        // Z'[k]
        FADD2(vi[q], Sei2, Ur);
        // advance angle by +pi/8
        float nc = cs * C8 - ss * S8;
        ss = ss * C8 + cs * S8;
        cs = nc;
    }
    LBAR(sub);

    // ---- inverse FFT ----
    fft8p<true>(vr, vi);
    store8p<1>(eR, eI, j, vr, vi);
    LBAR(sub);

    load8p(eR, eI, j, vr, vi);
    LBAR(sub);
    twiddle8p<true>(vr, vi, (j & 7) * (1.0f / 32.0f));
    fft8p<true>(vr, vi);
    store8p<8>(eR, eI, j, vr, vi);
    LBAR(sub);

    load8p(eR, eI, j, vr, vi);
    twiddle8p<true>(vr, vi, j * (1.0f / 256.0f));
    fft8p<true>(vr, vi);

    const float sc = 1.0f / 512.0f;
    float2* FoA = (float2*)(g_F[dst] + (b * TT + tA) * NFFTC);
    float2* FoB = FoA + 512;
#pragma unroll
    for (int q = 0; q < 8; q++) {
        int m = j + 64 * q;
        float2 w = swin2[m];
        float rA, rB, iA, iB;
        UPK2(vr[q], rA, rB);
        UPK2(vi[q], iA, iB);
        FoA[m] = make_float2(rA * w.x * sc, iA * w.y * sc);
        FoB[m] = make_float2(rB * w.x * sc, iB * w.y * sc);
    }
}

// ---------------------------------------------------------------------------
// Final: out = crop(OLA(F)/env)
// ---------------------------------------------------------------------------
__global__ void gl_final(float* __restrict__ out, int src) {
    int b  = blockIdx.y;
    int mm = blockIdx.x * 256 + threadIdx.x;   // LCROP = 1023*256 exactly
    int m  = mm + 512;
    const float* Fs = g_F[src] + b * (TT * NFFTC);
    int thi = min(m >> 8, TT - 1);
    int tlo = (m >= 768) ? ((m - 768) >> 8) : 0;
    float acc = 0.0f;
#pragma unroll
    for (int q = 0; q < 4; q++) {
        int tf = tlo + q;
        if (tf <= thi) acc += Fs[tf * NFFTC + (m - (tf << 8))];
    }
    out[b * LCROP + mm] = acc * g_invenv[m];
}

// ---------------------------------------------------------------------------
extern "C" void kernel_launch(void* const* d_in, const int* in_sizes, int n_in,
                              void* d_out, int out_size) {
    const float* mel    = (const float*)d_in[0];
    const float* angles = (const float*)d_in[1];
    const float* inv_fb = (const float*)d_in[2];
    float* out = (float*)d_out;

    gl_init_tables<<<(LPADL + 255) / 256, 256>>>();
    gl_mag<<<BB * 8, 256>>>(mel, inv_fb);
    gl_init_frames<<<BB * TT, 128>>>(angles);
    for (int i = 0; i < NITER; i++)
        gl_iter8<<<BB * (TT / FPB), 256>>>(i & 1, (i + 1) & 1);
    gl_final<<<dim3(LCROP / 256, BB), 256>>>(out, NITER & 1);
}

// round 15
// speedup vs baseline: 1.0479x; 1.0479x over previous
#include <cuda_runtime.h>

// ---------------------------------------------------------------------------
// Griffin-Lim, fully fused on-GPU.
//   mel (8,80,1024), angles (8,513,1024), inv_fb (513,80) -> out (8,261888)
// 60 iterations of istft -> stft -> phase projection in the FRAMES domain.
// Iteration kernel: register-resident radix-8^3 512-pt FFT, float2 ping-pong
// smem exchanges, DUAL-ANCHOR twiddle chains (depth<=3), per-lane named
// barriers, 4 blocks/SM (forced 64-reg target).
// ---------------------------------------------------------------------------

#define BB     8
#define TT     1024          // frames
#define NFFTC  1024
#define NFC    513
#define HOPC   256
#define LPADL  262912        // NFFT + (TT-1)*HOP
#define LCROP  261888        // (T-1)*HOP
#define FPB    4             // frames per block in iteration kernel
#define TILE   1792          // HOP*(FPB-1)+NFFT
#define REDGE  262400        // 512 + LCROP
#define MIRR   524798        // 2*LCROP + 1022
#define NITER  60

#define P8(x)  ((x) + ((x) >> 3))   // smem padding for exchange buffers
#define PBUF   576                  // P8(511)=574 < 576 (float2 entries)

// per-lane barrier: 64 threads (2 warps) of lane `sub`
#define LBAR(sub) asm volatile("bar.sync %0, 64;" :: "r"((sub) + 1) : "memory")

// Scratch (device globals are the sanctioned scratch mechanism)
__device__ float  g_F[2][BB * TT * NFFTC];   // istft frames, ping-pong (67 MB)
__device__ float  g_mag[BB * TT * NFC];      // target magnitudes [b][t][f]
__device__ float  g_win[NFFTC];
__device__ float2 g_tw[NFFTC];               // e^{-2*pi*i*m/1024} (init kernels only)
__device__ float  g_invenv[LPADL];           // 1 / window-envelope (or 1.0)

__device__ __forceinline__ void cmul(float ar, float ai, float br, float bi,
                                     float& cr, float& ci) {
    cr = ar * br - ai * bi;
    ci = ar * bi + ai * br;
}

// ===========================================================================
// Radix-8 register FFT machinery (512 = 8*8*8, 64 threads per FFT)
// ===========================================================================

template <bool INV>
__device__ __forceinline__ void fft8(float* vr, float* vi) {
    const float C = 0.70710678118654752440f;
    float a0r = vr[0] + vr[4], a0i = vi[0] + vi[4];
    float a1r = vr[0] - vr[4], a1i = vi[0] - vi[4];
    float b0r = vr[2] + vr[6], b0i = vi[2] + vi[6];
    float b1r = vr[2] - vr[6], b1i = vi[2] - vi[6];
    float w4br = INV ? -b1i : b1i;
    float w4bi = INV ?  b1r : -b1r;
    float E0r = a0r + b0r, E0i = a0i + b0i;
    float E2r = a0r - b0r, E2i = a0i - b0i;
    float E1r = a1r + w4br, E1i = a1i + w4bi;
    float E3r = a1r - w4br, E3i = a1i - w4bi;
    float c0r = vr[1] + vr[5], c0i = vi[1] + vi[5];
    float c1r = vr[1] - vr[5], c1i = vi[1] - vi[5];
    float d0r = vr[3] + vr[7], d0i = vi[3] + vi[7];
    float d1r = vr[3] - vr[7], d1i = vi[3] - vi[7];
    float w4dr = INV ? -d1i : d1i;
    float w4di = INV ?  d1r : -d1r;
    float O0r = c0r + d0r, O0i = c0i + d0i;
    float O2r = c0r - d0r, O2i = c0i - d0i;
    float O1r = c1r + w4dr, O1i = c1i + w4di;
    float O3r = c1r - w4dr, O3i = c1i - w4di;
    float t1r = INV ? C * (O1r - O1i) : C * (O1r + O1i);
    float t1i = INV ? C * (O1i + O1r) : C * (O1i - O1r);
    float t2r = INV ? -O2i : O2i;
    float t2i = INV ?  O2r : -O2r;
    float t3r = INV ? -C * (O3r + O3i) : C * (O3i - O3r);
    float t3i = INV ?  C * (O3r - O3i) : -C * (O3r + O3i);
    vr[0] = E0r + O0r; vi[0] = E0i + O0i;
    vr[4] = E0r - O0r; vi[4] = E0i - O0i;
    vr[1] = E1r + t1r; vi[1] = E1i + t1i;
    vr[5] = E1r - t1r; vi[5] = E1i - t1i;
    vr[2] = E2r + t2r; vi[2] = E2i + t2i;
    vr[6] = E2r - t2r; vi[6] = E2i - t2i;
    vr[3] = E3r + t3r; vi[3] = E3i + t3i;
    vr[7] = E3r - t3r; vi[7] = E3i - t3i;
}

__device__ __forceinline__ void load8v(const float2* ex, int j,
                                       float* vr, float* vi) {
#pragma unroll
    for (int q = 0; q < 8; q++) {
        int d = j + 64 * q;
        float2 v = ex[P8(d)];
        vr[q] = v.x; vi[q] = v.y;
    }
}

template <int NS>
__device__ __forceinline__ void store8v(float2* ex, int j,
                                        const float* vr, const float* vi) {
    int base = ((j & ~(NS - 1)) << 3) + (j & (NS - 1));
#pragma unroll
    for (int q = 0; q < 8; q++) {
        int d = base + q * NS;
        ex[P8(d)] = make_float2(vr[q], vi[q]);
    }
}

// Stockham stage twiddle: v[q] *= w^q, w = e^{-i pi ang_pi} (fwd) / conj (inv).
// DUAL-ANCHOR: sincospif at w^1 and w^4; chains q=1..3 and q=5..7, depth<=3.
template <bool INV>
__device__ __forceinline__ void twiddle8(float* vr, float* vi, float ang_pi) {
    float s1, c1, s4, c4;
    sincospif(ang_pi, &s1, &c1);
    sincospif(4.0f * ang_pi, &s4, &c4);
    if (!INV) { s1 = -s1; s4 = -s4; }
    // chain A: q = 1..3 from w^1
    float wr = c1, wi = s1;
#pragma unroll
    for (int q = 1; q <= 3; q++) {
        float tr = vr[q] * wr - vi[q] * wi;
        float ti = vr[q] * wi + vi[q] * wr;
        vr[q] = tr; vi[q] = ti;
        if (q < 3) {
            float nr = wr * c1 - wi * s1;
            wi = wr * s1 + wi * c1;
            wr = nr;
        }
    }
    // chain B: q = 4..7 from the w^4 anchor
    wr = c4; wi = s4;
#pragma unroll
    for (int q = 4; q < 8; q++) {
        float tr = vr[q] * wr - vi[q] * wi;
        float ti = vr[q] * wi + vi[q] * wr;
        vr[q] = tr; vi[q] = ti;
        if (q < 7) {
            float nr = wr * c1 - wi * s1;
            wi = wr * s1 + wi * c1;
            wr = nr;
        }
    }
}

// ===========================================================================
// Radix-4 shared-memory FFT (kept only for the one-time init kernel)
// ===========================================================================
template <int NS, bool INV>
__device__ __forceinline__ void stage4(const float* sr, const float* si,
                                       float* dr, float* di,
                                       const float2* tw, int j) {
    int i = j & (NS - 1);
    float x0r = sr[j],       x0i = si[j];
    float x1r = sr[j + 128], x1i = si[j + 128];
    float x2r = sr[j + 256], x2i = si[j + 256];
    float x3r = sr[j + 384], x3i = si[j + 384];
    if (NS > 1) {
        int ti = i * (256 / NS);
        float2 w1 = tw[ti], w2 = tw[2 * ti], w3 = tw[3 * ti];
        float w1i = INV ? -w1.y : w1.y;
        float w2i = INV ? -w2.y : w2.y;
        float w3i = INV ? -w3.y : w3.y;
        float tr, ti2;
        cmul(x1r, x1i, w1.x, w1i, tr, ti2); x1r = tr; x1i = ti2;
        cmul(x2r, x2i, w2.x, w2i, tr, ti2); x2r = tr; x2i = ti2;
        cmul(x3r, x3i, w3.x, w3i, tr, ti2); x3r = tr; x3i = ti2;
    }
    float t0r = x0r + x2r, t0i = x0i + x2i;
    float t1r = x0r - x2r, t1i = x0i - x2i;
    float t2r = x1r + x3r, t2i = x1i + x3i;
    float t3r = x1r - x3r, t3i = x1i - x3i;
    float jr = INV ? -t3i : t3i;
    float ji = INV ?  t3r : -t3r;
    int idxD = ((j & ~(NS - 1)) << 2) + i;
    dr[idxD]          = t0r + t2r;  di[idxD]          = t0i + t2i;
    dr[idxD + NS]     = t1r + jr;   di[idxD + NS]     = t1i + ji;
    dr[idxD + 2 * NS] = t0r - t2r;  di[idxD + 2 * NS] = t0i - t2i;
    dr[idxD + 3 * NS] = t1r - jr;   di[idxD + 3 * NS] = t1i - ji;
}

template <bool INV>
__device__ void fft512(float* r0, float* i0, float* r1, float* i1,
                       const float2* tw, int j) {
    __syncthreads();
    stage4<1,  INV>(r0, i0, r1, i1, tw, j); __syncthreads();
    stage4<4,  INV>(r1, i1, r0, i0, tw, j); __syncthreads();
    stage4<16, INV>(r0, i0, r1, i1, tw, j); __syncthreads();
    stage4<64, INV>(r1, i1, r0, i0, tw, j); __syncthreads();
#pragma unroll
    for (int q = 0; q < 2; q++) {
        int jj = j + q * 128;
        float x0r = r0[jj],       x0i = i0[jj];
        float x1r = r0[jj + 256], x1i = i0[jj + 256];
        float2 w  = tw[2 * jj];
        float wi = INV ? -w.y : w.y;
        float yr, yi;
        cmul(x1r, x1i, w.x, wi, yr, yi);
        r1[jj]       = x0r + yr;  i1[jj]       = x0i + yi;
        r1[jj + 256] = x0r - yr;  i1[jj + 256] = x0i - yi;
    }
    __syncthreads();
}

__device__ __forceinline__ void write_zprime(int k, float Pr, float Pi,
                                             float Qr, float Qi, float2 w,
                                             float* r0, float* i0) {
    float Ser = 0.5f * (Pr + Qr), Sei = 0.5f * (Pi - Qi);
    float Sdr = 0.5f * (Pr - Qr), Sdi = 0.5f * (Pi + Qi);
    float Ur = Sdr * w.x + Sdi * w.y;
    float Ui = Sdi * w.x - Sdr * w.y;
    r0[k] = Ser - Ui;
    i0[k] = Sei + Ur;
    if (k >= 1 && k <= 255) {
        r0[512 - k] = Ser + Ui;
        i0[512 - k] = Ur - Sei;
    }
}

// ---------------------------------------------------------------------------
// Table init: window, twiddles, inverse OLA envelope
// ---------------------------------------------------------------------------
__global__ void gl_init_tables() {
    int idx = blockIdx.x * blockDim.x + threadIdx.x;
    if (idx < NFFTC) {
        g_win[idx] = 0.5f - 0.5f * cospif(idx * (1.0f / 512.0f));
        float s, c;
        sincospif(idx * (1.0f / 512.0f), &s, &c);
        g_tw[idx] = make_float2(c, -s);
    }
    if (idx < LPADL) {
        int m   = idx;
        int thi = min(m >> 8, TT - 1);
        int tlo = (m >= 768) ? ((m - 768) >> 8) : 0;
        float e = 0.0f;
        for (int tf = tlo; tf <= thi; ++tf) {
            int kk  = m - (tf << 8);
            float w = 0.5f - 0.5f * cospif(kk * (1.0f / 512.0f));
            e += w * w;
        }
        g_invenv[idx] = (e > 1e-11f) ? (1.0f / e) : 1.0f;
    }
}

// ---------------------------------------------------------------------------
// mag = clip(inv_fb @ exp(mel), 0) -> g_mag[b][t][f]   (one-time)
// ---------------------------------------------------------------------------
__global__ __launch_bounds__(256) void gl_mag(const float* __restrict__ mel,
                                              const float* __restrict__ fb) {
    __shared__ float em[80 * 128];
    int tid = threadIdx.x;
    int bx  = blockIdx.x;
    int b   = bx >> 3;
    int t0  = (bx & 7) * 128;
    for (int idx = tid; idx < 80 * 128; idx += 256) {
        int m = idx >> 7, t = idx & 127;
        em[idx] = expf(mel[(b * 80 + m) * TT + t0 + t]);
    }
    __syncthreads();
    int t = tid & 127, half = tid >> 7;
    for (int f = half; f < NFC; f += 2) {
        const float* fbp = fb + f * 80;
        float acc = 0.0f;
#pragma unroll 16
        for (int m = 0; m < 80; m++) acc += fbp[m] * em[(m << 7) + t];
        g_mag[(b * TT + t0 + t) * NFC + f] = fmaxf(acc, 0.0f);
    }
}

// ---------------------------------------------------------------------------
// F0 = irfft(mag * e^{2 pi i angles}) * win   (one-time, radix-4 path)
// ---------------------------------------------------------------------------
__global__ __launch_bounds__(128) void gl_init_frames(const float* __restrict__ angles) {
    __shared__ float  r0[512], i0[512], r1[512], i1[512];
    __shared__ float  swin[NFFTC];
    __shared__ float2 stw[NFFTC];
    int tid = threadIdx.x;
    int bx  = blockIdx.x;
    int b   = bx >> 10;
    int t   = bx & 1023;
    for (int idx = tid; idx < NFFTC; idx += 128) {
        swin[idx] = g_win[idx];
        stw[idx]  = g_tw[idx];
    }
    const float* mp = &g_mag[(b * TT + t) * NFC];
    __syncthreads();
    for (int k = tid; k < 257; k += 128) {
        float a1 = angles[(b * NFC + k) * TT + t];
        float a2 = angles[(b * NFC + 512 - k) * TT + t];
        float s, c;
        sincospif(2.0f * a1, &s, &c);
        float m1 = mp[k];
        float Pr = m1 * c, Pi = m1 * s;
        sincospif(2.0f * a2, &s, &c);
        float m2 = mp[512 - k];
        float Qr = m2 * c, Qi = m2 * s;
        if (k == 0) { Pi = 0.0f; Qi = 0.0f; }
        write_zprime(k, Pr, Pi, Qr, Qi, stw[k], r0, i0);
    }
    fft512<true>(r0, i0, r1, i1, stw, tid);
    float* Fo = &g_F[0][(b * TT + t) * NFFTC];
    const float sc = 1.0f / 512.0f;
    for (int idx = tid; idx < NFFTC; idx += 128) {
        float v = (idx & 1) ? i1[idx >> 1] : r1[idx >> 1];
        Fo[idx] = v * swin[idx] * sc;
    }
}

// ---------------------------------------------------------------------------
// One Griffin-Lim step. 4 lanes x 64 threads; radix-8 register FFTs.
// float2 ping-pong exchanges (5 named barriers), 4 blocks/SM.
// ---------------------------------------------------------------------------
__global__ __launch_bounds__(256, 4) void gl_iter8(int src, int dst) {
    __shared__ float  sy[TILE];
    __shared__ float2 sEx[2][FPB * PBUF];
    __shared__ float2 swin2[512];
    int tid = threadIdx.x;
    int sub = tid >> 6;                 // FFT lane (frame) 0..3
    int j   = tid & 63;                 // thread within lane
    int bx  = blockIdx.x;
    int b   = bx >> 8;
    int g   = bx & 255;
    int t0  = g * FPB;
    int n0  = t0 * HOPC;

    const float2* gw2 = (const float2*)g_win;
    for (int idx = tid; idx < 512; idx += 256) swin2[idx] = gw2[idx];

    // --- gather normalized, reflect-padded signal tile (block-wide) ---
    const float* Fs = g_F[src] + b * (TT * NFFTC);
    if (g != 0 && g != 255) {
        // interior: m in [768, 262144), exactly 4 contributions, no reflect
        for (int u = tid; u < TILE; u += 256) {
            int m = n0 + u;
            const float* p = Fs + m + (((m >> 8) - 3) * 768);
            float acc = p[0] + p[768] + p[1536] + p[2304];
            sy[u] = acc * g_invenv[m];
        }
    } else {
        for (int u = tid; u < TILE; u += 256) {
            int m = n0 + u;
            if (m < 512)         m = 1024 - m;      // left reflect
            else if (m >= REDGE) m = MIRR - m;      // right reflect
            int thi = min(m >> 8, TT - 1);
            int tlo = (m >= 768) ? ((m - 768) >> 8) : 0;
            float acc = 0.0f;
#pragma unroll
            for (int qq = 0; qq < 4; qq++) {
                int tf = tlo + qq;
                if (tf <= thi) acc += Fs[tf * NFFTC + (m - (tf << 8))];
            }
            sy[u] = acc * g_invenv[m];
        }
    }
    __syncthreads();

    float2* ex0 = sEx[0] + sub * PBUF;
    float2* ex1 = sEx[1] + sub * PBUF;
    int t   = t0 + sub;
    int off = sub * HOPC;

    float vr[8], vi[8];

    // ---- forward FFT (packed real-1024 as complex-512) ----
    // stage 1 (Ns=1): pack straight from tile
#pragma unroll
    for (int q = 0; q < 8; q++) {
        int m = j + 64 * q;
        float2 w = swin2[m];
        vr[q] = sy[off + 2 * m]     * w.x;
        vi[q] = sy[off + 2 * m + 1] * w.y;
    }
    fft8<false>(vr, vi);
    store8v<1>(ex0, j, vr, vi);
    LBAR(sub);

    // stage 2 (Ns=8): ex0 -> ex1
    load8v(ex0, j, vr, vi);
    twiddle8<false>(vr, vi, (j & 7) * (1.0f / 32.0f));
    fft8<false>(vr, vi);
    store8v<8>(ex1, j, vr, vi);
    LBAR(sub);

    // stage 3 (Ns=64): ex1 -> regs -> Z natural order into ex0
    load8v(ex1, j, vr, vi);
    twiddle8<false>(vr, vi, j * (1.0f / 256.0f));
    fft8<false>(vr, vi);
#pragma unroll
    for (int q = 0; q < 8; q++) {
        int d = j + 64 * q;
        ex0[P8(d)] = make_float2(vr[q], vi[q]);
    }
    LBAR(sub);

    // ---- phase projection fused with inverse stage-1 input (reads ex0) ----
    // tw[k] for k = j+64q: anchors at q=0 and q=4, +pi/8 rotation chains
    const float* mp = g_mag + (b * TT + t) * NFC;
    const float C8 = 0.92387953251128675613f;   // cos(pi/8)
    const float S8 = 0.38268343236508977173f;   // sin(pi/8)
    float a0s, a0c, a4s, a4c;
    sincospif(j * (1.0f / 512.0f), &a0s, &a0c);
    sincospif((j + 256) * (1.0f / 512.0f), &a4s, &a4c);
    float cs = a0c, ssn = a0s;                  // (cos, sin)(2pi k/1024)
#pragma unroll
    for (int q = 0; q < 8; q++) {
        if (q == 4) { cs = a4c; ssn = a4s; }    // re-anchor
        int k  = j + 64 * q;
        int kc = (512 - k) & 511;
        float2 Pv = ex0[P8(k)];
        float2 Qv = ex0[P8(kc)];
        float Ser = 0.5f * (Pv.x + Qv.x), Sei = 0.5f * (Pv.y - Qv.y);
        float Sdr = 0.5f * (Pv.x - Qv.x), Sdi = 0.5f * (Pv.y + Qv.y);
        float c = cs, s = ssn;
        float A  =  Sdi * c - Sdr * s;
        float Bv = -Sdi * s - Sdr * c;
        float Xr = Ser + A,  Xi = Sei + Bv;     // X[k]
        float Yr = Ser - A,  Yi = Bv - Sei;     // X[512-k]
        float gk = mp[k]       * rsqrtf(Xr * Xr + Xi * Xi + 1e-16f);
        float gq = mp[512 - k] * rsqrtf(Yr * Yr + Yi * Yi + 1e-16f);
        float Gpr = gk * Xr, Gpi = gk * Xi;
        float Gqr = gq * Yr, Gqi = gq * Yi;
        float Ser2 = 0.5f * (Gpr + Gqr), Sei2 = 0.5f * (Gpi - Gqi);
        float Sdr2 = 0.5f * (Gpr - Gqr), Sdi2 = 0.5f * (Gpi + Gqi);
        float Ur = Sdr2 * c - Sdi2 * s;
        float Ui = Sdi2 * c + Sdr2 * s;
        vr[q] = Ser2 - Ui;                      // Z'[k]
        vi[q] = Sei2 + Ur;
        // advance angle by +pi/8
        float nc = cs * C8 - ssn * S8;
        ssn = ssn * C8 + cs * S8;
        cs = nc;
    }

    // ---- inverse FFT ----
    // stage 1 (Ns=1): regs -> ex1 (ex1's last readers synced at prior LBAR)
    fft8<true>(vr, vi);
    store8v<1>(ex1, j, vr, vi);
    LBAR(sub);

    // stage 2 (Ns=8): ex1 -> ex0 (phase reads of ex0 all precede this LBAR)
    load8v(ex1, j, vr, vi);
    twiddle8<true>(vr, vi, (j & 7) * (1.0f / 32.0f));
    fft8<true>(vr, vi);
    store8v<8>(ex0, j, vr, vi);
    LBAR(sub);

    // stage 3 (Ns=64): ex0 -> gmem, windowed, coalesced float2
    load8v(ex0, j, vr, vi);
    twiddle8<true>(vr, vi, j * (1.0f / 256.0f));
    fft8<true>(vr, vi);

    const float sc = 1.0f / 512.0f;
    float2* Fo = (float2*)(g_F[dst] + (b * TT + t) * NFFTC);
#pragma unroll
    for (int q = 0; q < 8; q++) {
        int m = j + 64 * q;
        float2 w = swin2[m];
        Fo[m] = make_float2(vr[q] * w.x * sc, vi[q] * w.y * sc);
    }
}

// ---------------------------------------------------------------------------
// Final: out = crop(OLA(F)/env)
// ---------------------------------------------------------------------------
__global__ void gl_final(float* __restrict__ out, int src) {
    int b  = blockIdx.y;
    int mm = blockIdx.x * 256 + threadIdx.x;   // LCROP = 1023*256 exactly
    int m  = mm + 512;
    const float* Fs = g_F[src] + b * (TT * NFFTC);
    int thi = min(m >> 8, TT - 1);
    int tlo = (m >= 768) ? ((m - 768) >> 8) : 0;
    float acc = 0.0f;
#pragma unroll
    for (int q = 0; q < 4; q++) {
        int tf = tlo + q;
        if (tf <= thi) acc += Fs[tf * NFFTC + (m - (tf << 8))];
    }
    out[b * LCROP + mm] = acc * g_invenv[m];
}

// ---------------------------------------------------------------------------
extern "C" void kernel_launch(void* const* d_in, const int* in_sizes, int n_in,
                              void* d_out, int out_size) {
    const float* mel    = (const float*)d_in[0];
    const float* angles = (const float*)d_in[1];
    const float* inv_fb = (const float*)d_in[2];
    float* out = (float*)d_out;

    gl_init_tables<<<(LPADL + 255) / 256, 256>>>();
    gl_mag<<<BB * 8, 256>>>(mel, inv_fb);
    gl_init_frames<<<BB * TT, 128>>>(angles);
    for (int i = 0; i < NITER; i++)
        gl_iter8<<<BB * (TT / FPB), 256>>>(i & 1, (i + 1) & 1);
    gl_final<<<dim3(LCROP / 256, BB), 256>>>(out, NITER & 1);
}

// round 17
// speedup vs baseline: 1.1342x; 1.0824x over previous
#include <cuda_runtime.h>

// ---------------------------------------------------------------------------
// Griffin-Lim, fully fused on-GPU.
//   mel (8,80,1024), angles (8,513,1024), inv_fb (513,80) -> out (8,261888)
// 60 iterations of istft -> stft -> phase projection in the FRAMES domain.
// Iteration kernel: register-resident radix-8^3 512-pt FFT, float2 ping-pong
// smem exchanges, chained twiddles, per-lane named barriers, 4 blocks/SM,
// float2-VECTORIZED interior OLA gather (pairwise-identical tap windows).
// ---------------------------------------------------------------------------

#define BB     8
#define TT     1024          // frames
#define NFFTC  1024
#define NFC    513
#define HOPC   256
#define LPADL  262912        // NFFT + (TT-1)*HOP
#define LCROP  261888        // (T-1)*HOP
#define FPB    4             // frames per block in iteration kernel
#define TILE   1792          // HOP*(FPB-1)+NFFT
#define REDGE  262400        // 512 + LCROP
#define MIRR   524798        // 2*LCROP + 1022
#define NITER  60

#define P8(x)  ((x) + ((x) >> 3))   // smem padding for exchange buffers
#define PBUF   576                  // P8(511)=574 < 576 (float2 entries)

// per-lane barrier: 64 threads (2 warps) of lane `sub`
#define LBAR(sub) asm volatile("bar.sync %0, 64;" :: "r"((sub) + 1) : "memory")

// Scratch (device globals are the sanctioned scratch mechanism)
__device__ float  g_F[2][BB * TT * NFFTC];   // istft frames, ping-pong (67 MB)
__device__ float  g_mag[BB * TT * NFC];      // target magnitudes [b][t][f]
__device__ float  g_win[NFFTC];
__device__ float2 g_tw[NFFTC];               // e^{-2*pi*i*m/1024} (init kernels only)
__device__ float  g_invenv[LPADL];           // 1 / window-envelope (or 1.0)

__device__ __forceinline__ void cmul(float ar, float ai, float br, float bi,
                                     float& cr, float& ci) {
    cr = ar * br - ai * bi;
    ci = ar * bi + ai * br;
}

// ===========================================================================
// Radix-8 register FFT machinery (512 = 8*8*8, 64 threads per FFT)
// ===========================================================================

template <bool INV>
__device__ __forceinline__ void fft8(float* vr, float* vi) {
    const float C = 0.70710678118654752440f;
    float a0r = vr[0] + vr[4], a0i = vi[0] + vi[4];
    float a1r = vr[0] - vr[4], a1i = vi[0] - vi[4];
    float b0r = vr[2] + vr[6], b0i = vi[2] + vi[6];
    float b1r = vr[2] - vr[6], b1i = vi[2] - vi[6];
    float w4br = INV ? -b1i : b1i;
    float w4bi = INV ?  b1r : -b1r;
    float E0r = a0r + b0r, E0i = a0i + b0i;
    float E2r = a0r - b0r, E2i = a0i - b0i;
    float E1r = a1r + w4br, E1i = a1i + w4bi;
    float E3r = a1r - w4br, E3i = a1i - w4bi;
    float c0r = vr[1] + vr[5], c0i = vi[1] + vi[5];
    float c1r = vr[1] - vr[5], c1i = vi[1] - vi[5];
    float d0r = vr[3] + vr[7], d0i = vi[3] + vi[7];
    float d1r = vr[3] - vr[7], d1i = vi[3] - vi[7];
    float w4dr = INV ? -d1i : d1i;
    float w4di = INV ?  d1r : -d1r;
    float O0r = c0r + d0r, O0i = c0i + d0i;
    float O2r = c0r - d0r, O2i = c0i - d0i;
    float O1r = c1r + w4dr, O1i = c1i + w4di;
    float O3r = c1r - w4dr, O3i = c1i - w4di;
    float t1r = INV ? C * (O1r - O1i) : C * (O1r + O1i);
    float t1i = INV ? C * (O1i + O1r) : C * (O1i - O1r);
    float t2r = INV ? -O2i : O2i;
    float t2i = INV ?  O2r : -O2r;
    float t3r = INV ? -C * (O3r + O3i) : C * (O3i - O3r);
    float t3i = INV ?  C * (O3r - O3i) : -C * (O3r + O3i);
    vr[0] = E0r + O0r; vi[0] = E0i + O0i;
    vr[4] = E0r - O0r; vi[4] = E0i - O0i;
    vr[1] = E1r + t1r; vi[1] = E1i + t1i;
    vr[5] = E1r - t1r; vi[5] = E1i - t1i;
    vr[2] = E2r + t2r; vi[2] = E2i + t2i;
    vr[6] = E2r - t2r; vi[6] = E2i - t2i;
    vr[3] = E3r + t3r; vi[3] = E3i + t3i;
    vr[7] = E3r - t3r; vi[7] = E3i - t3i;
}

__device__ __forceinline__ void load8v(const float2* ex, int j,
                                       float* vr, float* vi) {
#pragma unroll
    for (int q = 0; q < 8; q++) {
        int d = j + 64 * q;
        float2 v = ex[P8(d)];
        vr[q] = v.x; vi[q] = v.y;
    }
}

template <int NS>
__device__ __forceinline__ void store8v(float2* ex, int j,
                                        const float* vr, const float* vi) {
    int base = ((j & ~(NS - 1)) << 3) + (j & (NS - 1));
#pragma unroll
    for (int q = 0; q < 8; q++) {
        int d = base + q * NS;
        ex[P8(d)] = make_float2(vr[q], vi[q]);
    }
}

// Stockham stage twiddle: v[q] *= W512^{q*i*(512/(8*NS))}; chained cmul.
template <bool INV>
__device__ __forceinline__ void twiddle8(float* vr, float* vi, float ang_pi) {
    float s, c;
    sincospif(ang_pi, &s, &c);
    float w1r = c, w1i = INV ? s : -s;
    float wr = w1r, wi = w1i;
#pragma unroll
    for (int q = 1; q < 8; q++) {
        float tr = vr[q] * wr - vi[q] * wi;
        float ti = vr[q] * wi + vi[q] * wr;
        vr[q] = tr; vi[q] = ti;
        float nr = wr * w1r - wi * w1i;
        wi = wr * w1i + wi * w1r;
        wr = nr;
    }
}

// ===========================================================================
// Radix-4 shared-memory FFT (kept only for the one-time init kernel)
// ===========================================================================
template <int NS, bool INV>
__device__ __forceinline__ void stage4(const float* sr, const float* si,
                                       float* dr, float* di,
                                       const float2* tw, int j) {
    int i = j & (NS - 1);
    float x0r = sr[j],       x0i = si[j];
    float x1r = sr[j + 128], x1i = si[j + 128];
    float x2r = sr[j + 256], x2i = si[j + 256];
    float x3r = sr[j + 384], x3i = si[j + 384];
    if (NS > 1) {
        int ti = i * (256 / NS);
        float2 w1 = tw[ti], w2 = tw[2 * ti], w3 = tw[3 * ti];
        float w1i = INV ? -w1.y : w1.y;
        float w2i = INV ? -w2.y : w2.y;
        float w3i = INV ? -w3.y : w3.y;
        float tr, ti2;
        cmul(x1r, x1i, w1.x, w1i, tr, ti2); x1r = tr; x1i = ti2;
        cmul(x2r, x2i, w2.x, w2i, tr, ti2); x2r = tr; x2i = ti2;
        cmul(x3r, x3i, w3.x, w3i, tr, ti2); x3r = tr; x3i = ti2;
    }
    float t0r = x0r + x2r, t0i = x0i + x2i;
    float t1r = x0r - x2r, t1i = x0i - x2i;
    float t2r = x1r + x3r, t2i = x1i + x3i;
    float t3r = x1r - x3r, t3i = x1i - x3i;
    float jr = INV ? -t3i : t3i;
    float ji = INV ?  t3r : -t3r;
    int idxD = ((j & ~(NS - 1)) << 2) + i;
    dr[idxD]          = t0r + t2r;  di[idxD]          = t0i + t2i;
    dr[idxD + NS]     = t1r + jr;   di[idxD + NS]     = t1i + ji;
    dr[idxD + 2 * NS] = t0r - t2r;  di[idxD + 2 * NS] = t0i - t2i;
    dr[idxD + 3 * NS] = t1r - jr;   di[idxD + 3 * NS] = t1i - ji;
}

template <bool INV>
__device__ void fft512(float* r0, float* i0, float* r1, float* i1,
                       const float2* tw, int j) {
    __syncthreads();
    stage4<1,  INV>(r0, i0, r1, i1, tw, j); __syncthreads();
    stage4<4,  INV>(r1, i1, r0, i0, tw, j); __syncthreads();
    stage4<16, INV>(r0, i0, r1, i1, tw, j); __syncthreads();
    stage4<64, INV>(r1, i1, r0, i0, tw, j); __syncthreads();
#pragma unroll
    for (int q = 0; q < 2; q++) {
        int jj = j + q * 128;
        float x0r = r0[jj],       x0i = i0[jj];
        float x1r = r0[jj + 256], x1i = i0[jj + 256];
        float2 w  = tw[2 * jj];
        float wi = INV ? -w.y : w.y;
        float yr, yi;
        cmul(x1r, x1i, w.x, wi, yr, yi);
        r1[jj]       = x0r + yr;  i1[jj]       = x0i + yi;
        r1[jj + 256] = x0r - yr;  i1[jj + 256] = x0i - yi;
    }
    __syncthreads();
}

__device__ __forceinline__ void write_zprime(int k, float Pr, float Pi,
                                             float Qr, float Qi, float2 w,
                                             float* r0, float* i0) {
    float Ser = 0.5f * (Pr + Qr), Sei = 0.5f * (Pi - Qi);
    float Sdr = 0.5f * (Pr - Qr), Sdi = 0.5f * (Pi + Qi);
    float Ur = Sdr * w.x + Sdi * w.y;
    float Ui = Sdi * w.x - Sdr * w.y;
    r0[k] = Ser - Ui;
    i0[k] = Sei + Ur;
    if (k >= 1 && k <= 255) {
        r0[512 - k] = Ser + Ui;
        i0[512 - k] = Ur - Sei;
    }
}

// ---------------------------------------------------------------------------
// Table init: window, twiddles, inverse OLA envelope
// ---------------------------------------------------------------------------
__global__ void gl_init_tables() {
    int idx = blockIdx.x * blockDim.x + threadIdx.x;
    if (idx < NFFTC) {
        g_win[idx] = 0.5f - 0.5f * cospif(idx * (1.0f / 512.0f));
        float s, c;
        sincospif(idx * (1.0f / 512.0f), &s, &c);
        g_tw[idx] = make_float2(c, -s);
    }
    if (idx < LPADL) {
        int m   = idx;
        int thi = min(m >> 8, TT - 1);
        int tlo = (m >= 768) ? ((m - 768) >> 8) : 0;
        float e = 0.0f;
        for (int tf = tlo; tf <= thi; ++tf) {
            int kk  = m - (tf << 8);
            float w = 0.5f - 0.5f * cospif(kk * (1.0f / 512.0f));
            e += w * w;
        }
        g_invenv[idx] = (e > 1e-11f) ? (1.0f / e) : 1.0f;
    }
}

// ---------------------------------------------------------------------------
// mag = clip(inv_fb @ exp(mel), 0) -> g_mag[b][t][f]   (one-time)
// ---------------------------------------------------------------------------
__global__ __launch_bounds__(256) void gl_mag(const float* __restrict__ mel,
                                              const float* __restrict__ fb) {
    __shared__ float em[80 * 128];
    int tid = threadIdx.x;
    int bx  = blockIdx.x;
    int b   = bx >> 3;
    int t0  = (bx & 7) * 128;
    for (int idx = tid; idx < 80 * 128; idx += 256) {
        int m = idx >> 7, t = idx & 127;
        em[idx] = expf(mel[(b * 80 + m) * TT + t0 + t]);
    }
    __syncthreads();
    int t = tid & 127, half = tid >> 7;
    for (int f = half; f < NFC; f += 2) {
        const float* fbp = fb + f * 80;
        float acc = 0.0f;
#pragma unroll 16
        for (int m = 0; m < 80; m++) acc += fbp[m] * em[(m << 7) + t];
        g_mag[(b * TT + t0 + t) * NFC + f] = fmaxf(acc, 0.0f);
    }
}

// ---------------------------------------------------------------------------
// F0 = irfft(mag * e^{2 pi i angles}) * win   (one-time, radix-4 path)
// ---------------------------------------------------------------------------
__global__ __launch_bounds__(128) void gl_init_frames(const float* __restrict__ angles) {
    __shared__ float  r0[512], i0[512], r1[512], i1[512];
    __shared__ float  swin[NFFTC];
    __shared__ float2 stw[NFFTC];
    int tid = threadIdx.x;
    int bx  = blockIdx.x;
    int b   = bx >> 10;
    int t   = bx & 1023;
    for (int idx = tid; idx < NFFTC; idx += 128) {
        swin[idx] = g_win[idx];
        stw[idx]  = g_tw[idx];
    }
    const float* mp = &g_mag[(b * TT + t) * NFC];
    __syncthreads();
    for (int k = tid; k < 257; k += 128) {
        float a1 = angles[(b * NFC + k) * TT + t];
        float a2 = angles[(b * NFC + 512 - k) * TT + t];
        float s, c;
        sincospif(2.0f * a1, &s, &c);
        float m1 = mp[k];
        float Pr = m1 * c, Pi = m1 * s;
        sincospif(2.0f * a2, &s, &c);
        float m2 = mp[512 - k];
        float Qr = m2 * c, Qi = m2 * s;
        if (k == 0) { Pi = 0.0f; Qi = 0.0f; }
        write_zprime(k, Pr, Pi, Qr, Qi, stw[k], r0, i0);
    }
    fft512<true>(r0, i0, r1, i1, stw, tid);
    float* Fo = &g_F[0][(b * TT + t) * NFFTC];
    const float sc = 1.0f / 512.0f;
    for (int idx = tid; idx < NFFTC; idx += 128) {
        float v = (idx & 1) ? i1[idx >> 1] : r1[idx >> 1];
        Fo[idx] = v * swin[idx] * sc;
    }
}

// ---------------------------------------------------------------------------
// One Griffin-Lim step. 4 lanes x 64 threads; radix-8 register FFTs.
// float2 ping-pong exchanges (5 named barriers), 4 blocks/SM.
// Interior gather vectorized: even pairs (m, m+1) share the OLA tap window.
// ---------------------------------------------------------------------------
__global__ __launch_bounds__(256, 4) void gl_iter8(int src, int dst) {
    __shared__ float  sy[TILE];
    __shared__ float2 sEx[2][FPB * PBUF];
    __shared__ float2 swin2[512];
    int tid = threadIdx.x;
    int sub = tid >> 6;                 // FFT lane (frame) 0..3
    int j   = tid & 63;                 // thread within lane
    int bx  = blockIdx.x;
    int b   = bx >> 8;
    int g   = bx & 255;
    int t0  = g * FPB;
    int n0  = t0 * HOPC;

    const float2* gw2 = (const float2*)g_win;
    for (int idx = tid; idx < 512; idx += 256) swin2[idx] = gw2[idx];

    // --- gather normalized, reflect-padded signal tile (block-wide) ---
    const float* Fs = g_F[src] + b * (TT * NFFTC);
    if (g != 0 && g != 255) {
        // interior: m in [768, 262144): exactly 4 taps, no reflect.
        // For even m, elements m and m+1 share the same tap window
        // (boundaries only at m % 256 == 0, which is even), so process
        // float2 pairs: 4x LDG.64 + 1x LDG.64 per pair.
        for (int u2 = tid; u2 < TILE / 2; u2 += 256) {
            int m = n0 + 2 * u2;
            const float* p = Fs + m + (((m >> 8) - 3) * 768);
            float2 v0 = *(const float2*)(p);
            float2 v1 = *(const float2*)(p + 768);
            float2 v2 = *(const float2*)(p + 1536);
            float2 v3 = *(const float2*)(p + 2304);
            float2 e  = *(const float2*)(g_invenv + m);
            float2 r;
            r.x = (v0.x + v1.x + v2.x + v3.x) * e.x;
            r.y = (v0.y + v1.y + v2.y + v3.y) * e.y;
            *(float2*)(sy + 2 * u2) = r;
        }
    } else {
        for (int u = tid; u < TILE; u += 256) {
            int m = n0 + u;
            if (m < 512)         m = 1024 - m;      // left reflect
            else if (m >= REDGE) m = MIRR - m;      // right reflect
            int thi = min(m >> 8, TT - 1);
            int tlo = (m >= 768) ? ((m - 768) >> 8) : 0;
            float acc = 0.0f;
#pragma unroll
            for (int qq = 0; qq < 4; qq++) {
                int tf = tlo + qq;
                if (tf <= thi) acc += Fs[tf * NFFTC + (m - (tf << 8))];
            }
            sy[u] = acc * g_invenv[m];
        }
    }
    __syncthreads();

    float2* ex0 = sEx[0] + sub * PBUF;
    float2* ex1 = sEx[1] + sub * PBUF;
    int t   = t0 + sub;
    int off = sub * HOPC;

    float vr[8], vi[8];

    // ---- forward FFT (packed real-1024 as complex-512) ----
    // stage 1 (Ns=1): pack straight from tile
#pragma unroll
    for (int q = 0; q < 8; q++) {
        int m = j + 64 * q;
        float2 w = swin2[m];
        vr[q] = sy[off + 2 * m]     * w.x;
        vi[q] = sy[off + 2 * m + 1] * w.y;
    }
    fft8<false>(vr, vi);
    store8v<1>(ex0, j, vr, vi);
    LBAR(sub);

    // stage 2 (Ns=8): ex0 -> ex1
    load8v(ex0, j, vr, vi);
    twiddle8<false>(vr, vi, (j & 7) * (1.0f / 32.0f));
    fft8<false>(vr, vi);
    store8v<8>(ex1, j, vr, vi);
    LBAR(sub);

    // stage 3 (Ns=64): ex1 -> regs -> Z natural order into ex0
    load8v(ex1, j, vr, vi);
    twiddle8<false>(vr, vi, j * (1.0f / 256.0f));
    fft8<false>(vr, vi);
#pragma unroll
    for (int q = 0; q < 8; q++) {
        int d = j + 64 * q;
        ex0[P8(d)] = make_float2(vr[q], vi[q]);
    }
    LBAR(sub);

    // ---- phase projection fused with inverse stage-1 input (reads ex0) ----
    // tw[k] for k = j+64q computed as tw[j] * W64^q (chained)
    const float* mp = g_mag + (b * TT + t) * NFC;
    const float C8 = 0.92387953251128675613f;   // cos(pi/8)
    const float S8 = 0.38268343236508977173f;   // sin(pi/8)
    float wr, wi;
    {
        float s0, c0;
        sincospif(j * (1.0f / 512.0f), &s0, &c0);
        wr = c0; wi = -s0;                      // tw[j] = e^{-2pi i j/1024}
    }
#pragma unroll
    for (int q = 0; q < 8; q++) {
        int k  = j + 64 * q;
        int kc = (512 - k) & 511;
        float2 Pv = ex0[P8(k)];
        float2 Qv = ex0[P8(kc)];
        float Ser = 0.5f * (Pv.x + Qv.x), Sei = 0.5f * (Pv.y - Qv.y);
        float Sdr = 0.5f * (Pv.x - Qv.x), Sdi = 0.5f * (Pv.y + Qv.y);
        float c = wr, s = -wi;                  // (c, s) = (cos, sin)(2pi k/1024)
        float A  =  Sdi * c - Sdr * s;
        float Bv = -Sdi * s - Sdr * c;
        float Xr = Ser + A,  Xi = Sei + Bv;     // X[k]
        float Yr = Ser - A,  Yi = Bv - Sei;     // X[512-k]
        float gk = mp[k]       * rsqrtf(Xr * Xr + Xi * Xi + 1e-16f);
        float gq = mp[512 - k] * rsqrtf(Yr * Yr + Yi * Yi + 1e-16f);
        float Gpr = gk * Xr, Gpi = gk * Xi;
        float Gqr = gq * Yr, Gqi = gq * Yi;
        float Ser2 = 0.5f * (Gpr + Gqr), Sei2 = 0.5f * (Gpi - Gqi);
        float Sdr2 = 0.5f * (Gpr - Gqr), Sdi2 = 0.5f * (Gpi + Gqi);
        float Ur = Sdr2 * c - Sdi2 * s;
        float Ui = Sdi2 * c + Sdr2 * s;
        vr[q] = Ser2 - Ui;                      // Z'[k]
        vi[q] = Sei2 + Ur;
        // advance tw by W64 = (C8, -S8)
        float nr = wr * C8 + wi * S8;
        wi = wi * C8 - wr * S8;
        wr = nr;
    }

    // ---- inverse FFT ----
    // stage 1 (Ns=1): regs -> ex1 (ex1's last readers synced at prior LBAR)
    fft8<true>(vr, vi);
    store8v<1>(ex1, j, vr, vi);
    LBAR(sub);

    // stage 2 (Ns=8): ex1 -> ex0 (phase reads of ex0 all precede this LBAR)
    load8v(ex1, j, vr, vi);
    twiddle8<true>(vr, vi, (j & 7) * (1.0f / 32.0f));
    fft8<true>(vr, vi);
    store8v<8>(ex0, j, vr, vi);
    LBAR(sub);

    // stage 3 (Ns=64): ex0 -> gmem, windowed, coalesced float2
    load8v(ex0, j, vr, vi);
    twiddle8<true>(vr, vi, j * (1.0f / 256.0f));
    fft8<true>(vr, vi);

    const float sc = 1.0f / 512.0f;
    float2* Fo = (float2*)(g_F[dst] + (b * TT + t) * NFFTC);
#pragma unroll
    for (int q = 0; q < 8; q++) {
        int m = j + 64 * q;
        float2 w = swin2[m];
        Fo[m] = make_float2(vr[q] * w.x * sc, vi[q] * w.y * sc);
    }
}

// ---------------------------------------------------------------------------
// Final: out = crop(OLA(F)/env)
// ---------------------------------------------------------------------------
__global__ void gl_final(float* __restrict__ out, int src) {
    int b  = blockIdx.y;
    int mm = blockIdx.x * 256 + threadIdx.x;   // LCROP = 1023*256 exactly
    int m  = mm + 512;
    const float* Fs = g_F[src] + b * (TT * NFFTC);
    int thi = min(m >> 8, TT - 1);
    int tlo = (m >= 768) ? ((m - 768) >> 8) : 0;
    float acc = 0.0f;
#pragma unroll
    for (int q = 0; q < 4; q++) {
        int tf = tlo + q;
        if (tf <= thi) acc += Fs[tf * NFFTC + (m - (tf << 8))];
    }
    out[b * LCROP + mm] = acc * g_invenv[m];
}

// ---------------------------------------------------------------------------
extern "C" void kernel_launch(void* const* d_in, const int* in_sizes, int n_in,
                              void* d_out, int out_size) {
    const float* mel    = (const float*)d_in[0];
    const float* angles = (const float*)d_in[1];
    const float* inv_fb = (const float*)d_in[2];
    float* out = (float*)d_out;

    gl_init_tables<<<(LPADL + 255) / 256, 256>>>();
    gl_mag<<<BB * 8, 256>>>(mel, inv_fb);
    gl_init_frames<<<BB * TT, 128>>>(angles);
    for (int i = 0; i < NITER; i++)
        gl_iter8<<<BB * (TT / FPB), 256>>>(i & 1, (i + 1) & 1);
    gl_final<<<dim3(LCROP / 256, BB), 256>>>(out, NITER & 1);
}